// round 6
// baseline (speedup 1.0000x reference)
#include <cuda_runtime.h>
#include <math.h>

#define HID 1024
#define VOC 50257
#define SEQ 512
#define N4  12564   // floor(VOC/4); element VOC-1 handled scalar

__device__ __align__(16) float g_alog[SEQ];        // attention logits
__device__ __align__(16) float g_w[SEQ];           // softmax weights
__device__ __align__(16) float g_papp[4 * HID];    // partial attn_applied (4 i-chunks)
__device__ __align__(16) float g_x[HID];           // relu(comb) output
__device__ __align__(16) float g_gih[6 * HID];     // [gi_r gi_z gi_n gh_r gh_z gh_n]
__device__ __align__(16) float g_logits[VOC + 3];  // padded for float4
__device__ float g_red[2];                         // max, log(sum exp)
__device__ int   g_ctr1, g_ctr2, g_ctr3;

__device__ __forceinline__ float wsum(float v) {
#pragma unroll
    for (int o = 16; o; o >>= 1) v += __shfl_xor_sync(0xffffffffu, v, o);
    return v;
}
__device__ __forceinline__ float wmax(float v) {
#pragma unroll
    for (int o = 16; o; o >>= 1) v = fmaxf(v, __shfl_xor_sync(0xffffffffu, v, o));
    return v;
}

// K1: blocks [0,256): attn logits split-K x4 (+softmax tail via counter).
//     blocks [256,448): gh = W_hh @ h0 (2 rows/warp) -> g_gih[3H..6H).
__global__ void __launch_bounds__(256, 2)
k_attn_gh(const int* __restrict__ tok, const float* __restrict__ hid,
          const float* __restrict__ emb, const float* __restrict__ attn_W,
          const float* __restrict__ attn_b, const float* __restrict__ W_hh,
          float* __restrict__ out_attn) {
    int t = threadIdx.x, w = t >> 5, lane = t & 31;

    if (blockIdx.x >= 256) {
        // ---- gh part ----
        __shared__ __align__(16) float vs[HID];
        for (int i = t; i < HID; i += 256) vs[i] = hid[i];
        __syncthreads();
        int r0 = (blockIdx.x - 256) * 16 + w * 2;
        const float4* m0 = (const float4*)(W_hh + (long)r0 * HID);
        const float4* m1 = (const float4*)(W_hh + (long)(r0 + 1) * HID);
        const float4* c  = (const float4*)vs;
        float s0 = 0.f, s1 = 0.f;
#pragma unroll
        for (int i = 0; i < 8; i++) {
            int k = lane + 32 * i;
            float4 b  = c[k];
            float4 a0 = __ldcs(m0 + k);
            float4 a1 = __ldcs(m1 + k);
            s0 += a0.x * b.x + a0.y * b.y + a0.z * b.z + a0.w * b.w;
            s1 += a1.x * b.x + a1.y * b.y + a1.z * b.z + a1.w * b.w;
        }
        s0 = wsum(s0); s1 = wsum(s1);
        if (lane == 0) { g_gih[3 * HID + r0] = s0; g_gih[3 * HID + r0 + 1] = s1; }
        return;
    }

    // ---- attn logits part ----
    int gw = blockIdx.x * 8 + w;
    int row = gw >> 2;
    int kc  = gw & 3;
    const float* er = emb + (long)tok[0] * HID;
    const float* base = (kc < 2) ? (er + kc * 512) : (hid + (kc - 2) * 512);
    const float4* m = (const float4*)(attn_W + (long)row * 2 * HID + kc * 512);
    const float4* c = (const float4*)base;
    float s = 0.f;
#pragma unroll
    for (int i = 0; i < 4; i++) {
        float4 a = m[lane + 32 * i], b = c[lane + 32 * i];
        s += a.x * b.x + a.y * b.y + a.z * b.z + a.w * b.w;
    }
    s = wsum(s);
    __shared__ float p[8];
    __shared__ int s_last;
    if (lane == 0) p[w] = s;
    __syncthreads();
    if (t < 2) {
        int r = blockIdx.x * 2 + t;
        g_alog[r] = p[4 * t] + p[4 * t + 1] + p[4 * t + 2] + p[4 * t + 3] + attn_b[r];
    }
    __syncthreads();
    if (t == 0) { __threadfence(); s_last = (atomicAdd(&g_ctr1, 1) == 255); }
    __syncthreads();
    if (!s_last) return;
    // ---- last attn block: softmax over 512 ----
    __threadfence();
    if (t == 0) g_ctr1 = 0;
    __shared__ float red[8];
    __shared__ float bcM, bcS;
    float v0 = g_alog[t], v1 = g_alog[t + 256];
    float mx = wmax(fmaxf(v0, v1));
    if (lane == 0) red[w] = mx;
    __syncthreads();
    if (t < 32) { float x = (t < 8) ? red[t] : -1e30f; x = wmax(x); if (t == 0) bcM = x; }
    __syncthreads();
    float e0 = __expf(v0 - bcM), e1 = __expf(v1 - bcM);
    float ss = wsum(e0 + e1);
    if (lane == 0) red[w] = ss;
    __syncthreads();
    if (t < 32) { float x = (t < 8) ? red[t] : 0.f; x = wsum(x); if (t == 0) bcS = x; }
    __syncthreads();
    float inv = 1.f / bcS;
    float w0 = e0 * inv, w1 = e1 * inv;
    g_w[t] = w0; g_w[t + 256] = w1;
    out_attn[t] = w0; out_attn[t + 256] = w1;
}

// K2: partial attn_applied. 16 blocks = 4 j-blocks x 4 i-chunks (no atomics).
__global__ void __launch_bounds__(256, 2) k_app(const float* __restrict__ enc) {
    int t = threadIdx.x;
    __shared__ float w[128];
    int jb = blockIdx.x & 3, ic = blockIdx.x >> 2;
    if (t < 128) w[t] = g_w[ic * 128 + t];
    __syncthreads();
    int j = jb * 256 + t;
    const float* ep = enc + (long)ic * 128 * HID + j;
    float acc = 0.f;
#pragma unroll 16
    for (int i = 0; i < 128; i++) acc += w[i] * __ldcs(ep + (long)i * HID);
    g_papp[ic * HID + j] = acc;
}

// K3: x = relu([embed, attn_applied] @ comb_W.T + b), split-K x4 (512 blocks x 256).
__global__ void __launch_bounds__(256, 2)
k_comb(const int* __restrict__ tok, const float* __restrict__ emb,
       const float* __restrict__ comb_W, const float* __restrict__ comb_b) {
    int t = threadIdx.x, w = t >> 5, lane = t & 31;
    int gw = blockIdx.x * 8 + w;
    int row = gw >> 2;
    int kc  = gw & 3;
    const float4* m = (const float4*)(comb_W + (long)row * 2 * HID + kc * 512);
    float s = 0.f;
    if (kc < 2) {
        const float4* c = (const float4*)(emb + (long)tok[0] * HID + kc * 512);
#pragma unroll
        for (int i = 0; i < 4; i++) {
            int k = lane + 32 * i;
            float4 a = __ldcs(m + k), b = c[k];
            s += a.x * b.x + a.y * b.y + a.z * b.z + a.w * b.w;
        }
    } else {
        const float4* p0 = (const float4*)(g_papp + 0 * HID + (kc - 2) * 512);
        const float4* p1 = (const float4*)(g_papp + 1 * HID + (kc - 2) * 512);
        const float4* p2 = (const float4*)(g_papp + 2 * HID + (kc - 2) * 512);
        const float4* p3 = (const float4*)(g_papp + 3 * HID + (kc - 2) * 512);
#pragma unroll
        for (int i = 0; i < 4; i++) {
            int k = lane + 32 * i;
            float4 a = __ldcs(m + k);
            float4 q0 = p0[k], q1 = p1[k], q2 = p2[k], q3 = p3[k];
            s += a.x * (q0.x + q1.x + q2.x + q3.x)
               + a.y * (q0.y + q1.y + q2.y + q3.y)
               + a.z * (q0.z + q1.z + q2.z + q3.z)
               + a.w * (q0.w + q1.w + q2.w + q3.w);
        }
    }
    s = wsum(s);
    __shared__ float p[8];
    if (lane == 0) p[w] = s;
    __syncthreads();
    if (t < 2) {
        int r = blockIdx.x * 2 + t;
        float v = p[4 * t] + p[4 * t + 1] + p[4 * t + 2] + p[4 * t + 3] + comb_b[r];
        g_x[r] = fmaxf(v, 0.f);
    }
}

// K4: gi = W_ih @ x (3072 rows, 2 rows/warp, 192 blocks) + gate tail in last block.
__global__ void __launch_bounds__(256, 2)
k_gi(const float* __restrict__ hid, const float* __restrict__ W_ih,
     const float* __restrict__ b_ih, const float* __restrict__ b_hh,
     float* __restrict__ out_h) {
    __shared__ __align__(16) float vs[HID];
    __shared__ int s_last;
    int t = threadIdx.x, w = t >> 5, lane = t & 31;
    for (int i = t; i < HID; i += 256) vs[i] = g_x[i];
    __syncthreads();
    int r0 = blockIdx.x * 16 + w * 2;
    const float4* m0 = (const float4*)(W_ih + (long)r0 * HID);
    const float4* m1 = (const float4*)(W_ih + (long)(r0 + 1) * HID);
    const float4* c  = (const float4*)vs;
    float s0 = 0.f, s1 = 0.f;
#pragma unroll
    for (int i = 0; i < 8; i++) {
        int k = lane + 32 * i;
        float4 b  = c[k];
        float4 a0 = __ldcs(m0 + k);
        float4 a1 = __ldcs(m1 + k);
        s0 += a0.x * b.x + a0.y * b.y + a0.z * b.z + a0.w * b.w;
        s1 += a1.x * b.x + a1.y * b.y + a1.z * b.z + a1.w * b.w;
    }
    s0 = wsum(s0); s1 = wsum(s1);
    if (lane == 0) { g_gih[r0] = s0; g_gih[r0 + 1] = s1; }
    __syncthreads();
    if (t == 0) { __threadfence(); s_last = (atomicAdd(&g_ctr2, 1) == (int)gridDim.x - 1); }
    __syncthreads();
    if (!s_last) return;
    __threadfence();
    if (t == 0) g_ctr2 = 0;
    for (int j = t; j < HID; j += 256) {
        float ir  = g_gih[j]           + b_ih[j];
        float iz  = g_gih[HID + j]     + b_ih[HID + j];
        float in_ = g_gih[2 * HID + j] + b_ih[2 * HID + j];
        float hr  = g_gih[3 * HID + j] + b_hh[j];
        float hz  = g_gih[4 * HID + j] + b_hh[HID + j];
        float hn  = g_gih[5 * HID + j] + b_hh[2 * HID + j];
        float r = 1.f / (1.f + __expf(-(ir + hr)));
        float z = 1.f / (1.f + __expf(-(iz + hz)));
        float n = tanhf(in_ + r * hn);
        out_h[j] = (1.f - z) * n + z * hid[j];
    }
}

// K5: logits = h_new @ out_W.T + out_b (206 MB; 4 rows/warp) + LSE tail in last block.
__global__ void __launch_bounds__(256, 2)
k_out(const float* __restrict__ out_h, const float* __restrict__ out_W,
      const float* __restrict__ out_b) {
    __shared__ __align__(16) float h[HID];
    __shared__ int s_last;
    int t = threadIdx.x, w = t >> 5, lane = t & 31;
    for (int i = t; i < HID; i += 256) h[i] = out_h[i];
    __syncthreads();
    int r0 = blockIdx.x * 32 + w * 4;
    if (r0 < VOC) {
        int r1 = min(r0 + 1, VOC - 1);
        int r2 = min(r0 + 2, VOC - 1);
        int r3 = min(r0 + 3, VOC - 1);
        const float4* c  = (const float4*)h;
        const float4* m0 = (const float4*)(out_W + (long)r0 * HID);
        const float4* m1 = (const float4*)(out_W + (long)r1 * HID);
        const float4* m2 = (const float4*)(out_W + (long)r2 * HID);
        const float4* m3 = (const float4*)(out_W + (long)r3 * HID);
        float s0 = 0.f, s1 = 0.f, s2 = 0.f, s3 = 0.f;
#pragma unroll
        for (int i = 0; i < 8; i++) {
            int k = lane + 32 * i;
            float4 b  = c[k];
            float4 a0 = __ldcs(m0 + k);
            float4 a1 = __ldcs(m1 + k);
            float4 a2 = __ldcs(m2 + k);
            float4 a3 = __ldcs(m3 + k);
            s0 += a0.x * b.x + a0.y * b.y + a0.z * b.z + a0.w * b.w;
            s1 += a1.x * b.x + a1.y * b.y + a1.z * b.z + a1.w * b.w;
            s2 += a2.x * b.x + a2.y * b.y + a2.z * b.z + a2.w * b.w;
            s3 += a3.x * b.x + a3.y * b.y + a3.z * b.z + a3.w * b.w;
        }
        s0 = wsum(s0); s1 = wsum(s1); s2 = wsum(s2); s3 = wsum(s3);
        if (lane == 0) {
            g_logits[r0] = s0 + out_b[r0];
            if (r0 + 1 < VOC) g_logits[r0 + 1] = s1 + out_b[r0 + 1];
            if (r0 + 2 < VOC) g_logits[r0 + 2] = s2 + out_b[r0 + 2];
            if (r0 + 3 < VOC) g_logits[r0 + 3] = s3 + out_b[r0 + 3];
        }
    }
    __syncthreads();
    if (t == 0) { __threadfence(); s_last = (atomicAdd(&g_ctr3, 1) == (int)gridDim.x - 1); }
    __syncthreads();
    if (!s_last) return;
    // ---- last block: online logsumexp over logits (L2-resident) ----
    __threadfence();
    if (t == 0) g_ctr3 = 0;
    __shared__ float shm[8], shs[8];
    const float4* L4 = (const float4*)g_logits;
    float m = -1e30f, s = 0.f;
    for (int i = t; i < N4; i += 256) {
        float4 v = L4[i];
        float lm = fmaxf(fmaxf(v.x, v.y), fmaxf(v.z, v.w));
        if (lm > m) { s = s * __expf(m - lm); m = lm; }
        s += __expf(v.x - m) + __expf(v.y - m) + __expf(v.z - m) + __expf(v.w - m);
    }
    if (t == 0) {
        float v = g_logits[VOC - 1];
        if (v > m) { s = s * __expf(m - v); m = v; }
        s += __expf(v - m);
    }
#pragma unroll
    for (int o = 16; o; o >>= 1) {
        float om = __shfl_xor_sync(0xffffffffu, m, o);
        float os = __shfl_xor_sync(0xffffffffu, s, o);
        if (om > m) { s = s * __expf(m - om) + os; m = om; }
        else          s += os * __expf(om - m);
    }
    if (lane == 0) { shm[w] = m; shs[w] = s; }
    __syncthreads();
    if (t == 0) {
        float M = shm[0], S = shs[0];
        for (int i = 1; i < 8; i++) {
            float om = shm[i], os = shs[i];
            if (om > M) { S = S * __expf(M - om) + os; M = om; }
            else          S += os * __expf(om - M);
        }
        g_red[0] = M; g_red[1] = logf(S);
    }
}

// K6: logp = logits - (max + logsum)   (13 blocks x 1024, float4)
__global__ void __launch_bounds__(1024) k_logp(float* __restrict__ out) {
    float off = g_red[0] + g_red[1];
    int i = blockIdx.x * 1024 + threadIdx.x;
    if (i < N4) {
        float4 v = ((const float4*)g_logits)[i];
        v.x -= off; v.y -= off; v.z -= off; v.w -= off;
        ((float4*)out)[i] = v;
    }
    if (i == 0) out[VOC - 1] = g_logits[VOC - 1] - off;
}

extern "C" void kernel_launch(void* const* d_in, const int* in_sizes, int n_in,
                              void* d_out, int out_size) {
    const int*   tok    = (const int*)d_in[0];
    const float* hidden = (const float*)d_in[1];
    const float* enc    = (const float*)d_in[2];
    const float* emb    = (const float*)d_in[3];
    const float* attn_W = (const float*)d_in[4];
    const float* attn_b = (const float*)d_in[5];
    const float* comb_W = (const float*)d_in[6];
    const float* comb_b = (const float*)d_in[7];
    const float* W_ih   = (const float*)d_in[8];
    const float* W_hh   = (const float*)d_in[9];
    const float* b_ih   = (const float*)d_in[10];
    const float* b_hh   = (const float*)d_in[11];
    const float* out_W  = (const float*)d_in[12];
    const float* out_b  = (const float*)d_in[13];

    float* out      = (float*)d_out;         // logp  [50257]
    float* out_h    = out + VOC;             // h_new [1024]
    float* out_attn = out + VOC + HID;       // attn_weights [512]

    k_attn_gh<<<448, 256>>>(tok, hidden, emb, attn_W, attn_b, W_hh, out_attn);
    k_app<<<16, 256>>>(enc);
    k_comb<<<512, 256>>>(tok, emb, comb_W, comb_b);
    k_gi<<<192, 256>>>(hidden, W_ih, b_ih, b_hh, out_h);
    k_out<<<(VOC + 31) / 32, 256>>>(out_h, out_W, out_b);
    k_logp<<<(N4 + 1023) / 1024, 1024>>>(out);
}